// round 14
// baseline (speedup 1.0000x reference)
#include <cuda_runtime.h>
#include <mma.h>
#include <math.h>

using namespace nvcuda;

#define NB 8192

// ---------------- device scratch ----------------
// g_y0: conv0 output in conv1-B layout [n][128][196] (822MB). Dead after k_conv1;
//       g_y2 aliases its head.
__device__ float  g_y0[(size_t)NB * 128 * 196];
// g_y1: conv1 output in conv2-B layout [n][256][49] (411MB)
__device__ float  g_y1[(size_t)NB * 256 * 49];
#define g_y2 g_y0                                     // conv2 pre-BN output [n][128][49]
__device__ double g_acc[448];
__device__ float  g_scale[224];
__device__ float  g_shift[224];

__device__ __forceinline__ float tf32r(float x) {
    float y;
    asm("cvt.rna.tf32.f32 %0, %1;" : "=f"(y) : "f"(x));
    return y;
}

// ---------------- zero stats ----------------
__global__ void k_zero() {
    int i = blockIdx.x * blockDim.x + threadIdx.x;
    if (i < 448) g_acc[i] = 0.0;
}

// ---------------- stage0: conv0 (+bias) -> y0 (permuted), stats ----------------
// y0 row = c*4 + (r&1)*2 + (col&1), p = (r>>1)*14 + (col>>1)
__global__ void __launch_bounds__(256) k_stats0(const float* __restrict__ x,
                                                const float* __restrict__ w0,
                                                const float* __restrict__ b0) {
    __shared__ float sx[30 * 28];
    __shared__ float sw[288];
    __shared__ float sb[32];
    __shared__ float ssum[32], ssq[32];
    int tid = threadIdx.x;
    int n = blockIdx.x;
    const float* xim = x + (size_t)n * 784;
    for (int i = tid; i < 840; i += 256) {
        int r = i / 28;
        sx[i] = (r >= 1 && r <= 28) ? xim[i - 28] : 0.f;
    }
    for (int i = tid; i < 288; i += 256) sw[i] = w0[i];
    if (tid < 32) { sb[tid] = b0[tid]; ssum[tid] = 0.f; ssq[tid] = 0.f; }
    __syncthreads();

#define LDROW(SR, X0, X1, X2) { const float* _p = &sx[(SR) * 28 + col]; \
        X0 = mL ? _p[-1] : 0.f; X1 = _p[0]; X2 = mR ? _p[1] : 0.f; }

    for (int task = tid; task < 896; task += 256) {
        int c = task / 28, col = task % 28;
        float w[9];
#pragma unroll
        for (int i = 0; i < 9; i++) w[i] = sw[c * 9 + i];
        float bias = sb[c];
        bool mL = col > 0, mR = col < 27;
        int rowbase = c * 4 + (col & 1);
        float* d0 = g_y0 + ((size_t)n * 128 + rowbase) * 196 + (col >> 1);
        float* d1 = d0 + 2 * 196;
        float a0, a1, a2, d00, d01, d02, e0, e1, e2;
        LDROW(0, a0, a1, a2);
        LDROW(1, d00, d01, d02);
        float ls = 0.f, lq = 0.f;
        for (int r = 0; r < 28; r++) {
            LDROW(r + 2, e0, e1, e2);
            float acc = bias;
            acc += w[0] * a0 + w[1] * a1 + w[2] * a2;
            acc += w[3] * d00 + w[4] * d01 + w[5] * d02;
            acc += w[6] * e0 + w[7] * e1 + w[8] * e2;
            ((r & 1) ? d1 : d0)[(r >> 1) * 14] = acc;
            ls += acc; lq += acc * acc;
            a0 = d00; a1 = d01; a2 = d02;
            d00 = e0; d01 = e1; d02 = e2;
        }
        atomicAdd(&ssum[c], ls);
        atomicAdd(&ssq[c], lq);
    }
    __syncthreads();
    if (tid < 32) {
        atomicAdd(&g_acc[tid], (double)ssum[tid]);
        atomicAdd(&g_acc[32 + tid], (double)ssq[tid]);
    }
}

// ---------------- finalize BN ----------------
__global__ void k_fin(int acc_off, int C, double inv_n,
                      const float* __restrict__ g, const float* __restrict__ be, int so) {
    int c = threadIdx.x;
    if (c < C) {
        double mean = g_acc[acc_off + c] * inv_n;
        double var = g_acc[acc_off + C + c] * inv_n - mean * mean;
        float s = g[c] * rsqrtf((float)var + 1e-5f);
        g_scale[so + c] = s;
        g_shift[so + c] = be[c] - (float)mean * s;
    }
}

// ---------------- bn0+relu(y0) -> conv1 (WMMA tf32) -> y1 (permuted), stats1 ----
// block = half image, 512 threads (16 warps), 2 blocks/SM (regs capped at 64).
// Warp (Nt 0..7[7 idle], Mg 0..1): 2 Mtiles x 1 Ntile.
// smem floats: B [128][136] 17408 | W [64][136] 8704 | ssum 64 | ssq 64 = 104960 B
__global__ void __launch_bounds__(512, 2) k_conv1(const float* __restrict__ w1,
                                                  const float* __restrict__ b1) {
    extern __shared__ float sm[];
    float* B    = sm;            // [128][136]
    float* W    = sm + 17408;    // [64][136]
    float* ssum = sm + 26112;    // 64
    float* ssq  = sm + 26176;    // 64

    int tid = threadIdx.x;
    int n = blockIdx.x >> 1;
    int half = blockIdx.x & 1;

    if (tid < 64) { ssum[tid] = 0.f; ssq[tid] = 0.f; }
    for (int i = tid; i < 8192; i += 512) {
        int co = i >> 7, k = i & 127;
        W[co * 136 + k] = tf32r(w1[i]);
    }
    // zero B pad columns p=98..111
    for (int i = tid; i < 1792; i += 512) {
        B[(i / 14) * 136 + 98 + (i % 14)] = 0.f;
    }
    __syncthreads();

    // B-build: coalesced float2 copy + bn0 + relu + tf32
    const float* y0b = g_y0 + (size_t)n * 128 * 196 + half * 98;
    for (int idx = tid; idx < 6272; idx += 512) {   // 128 rows x 49 float2
        int row = idx / 49;
        int j = idx - row * 49;
        float sc = g_scale[row >> 2], sh = g_shift[row >> 2];
        float2 v = *(const float2*)(y0b + (size_t)row * 196 + 2 * j);
        B[row * 136 + 2 * j]     = tf32r(fmaxf(fmaf(v.x, sc, sh), 0.f));
        B[row * 136 + 2 * j + 1] = tf32r(fmaxf(fmaf(v.y, sc, sh), 0.f));
    }
    __syncthreads();

    // WMMA: warp (Nt, Mg), Nt = wpi&7 (0..6 used), Mg = wpi>>3, 2 Mtiles each
    int wpi = tid >> 5;
    int Nt = wpi & 7, Mg = wpi >> 3;
    wmma::fragment<wmma::accumulator, 16, 16, 8, float> cf[2];
    if (Nt < 7) {
#pragma unroll
        for (int m = 0; m < 2; m++) wmma::fill_fragment(cf[m], 0.f);
        wmma::fragment<wmma::matrix_a, 16, 16, 8, wmma::precision::tf32, wmma::row_major> af;
        wmma::fragment<wmma::matrix_b, 16, 16, 8, wmma::precision::tf32, wmma::row_major> bf;
#pragma unroll 4
        for (int ks = 0; ks < 16; ks++) {
            wmma::load_matrix_sync(bf, &B[ks * 8 * 136 + Nt * 16], 136);
#pragma unroll
            for (int m = 0; m < 2; m++) {
                int Mt = Mg * 2 + m;
                wmma::load_matrix_sync(af, &W[Mt * 16 * 136 + ks * 8], 136);
                wmma::mma_sync(cf[m], af, bf, cf[m]);
            }
        }
    }
    __syncthreads();   // all B reads done -> store C over B region
    if (Nt < 7) {
#pragma unroll
        for (int m = 0; m < 2; m++) {
            int Mt = Mg * 2 + m;
            wmma::store_matrix_sync(&B[Mt * 16 * 136 + Nt * 16], cf[m], 136,
                                    wmma::mem_row_major);
        }
    }
    __syncthreads();

    // bias + stats + permuted y1 write ([n][256][49]) — 8 threads per co row
    {
        int co = tid >> 3, q = tid & 7;
        int p0 = q * 13, cnt = (q < 7) ? 13 : 7;
        float bias = b1[co];
        float ls = 0.f, lq = 0.f;
        const float* src = &B[co * 136 + p0];
        float* y1n = g_y1 + (size_t)n * 256 * 49;
#pragma unroll 13
        for (int i = 0; i < cnt; i++) {
            int p = p0 + i;
            int oh_l = p / 14, ow = p - oh_l * 14;
            int oh = half * 7 + oh_l;
            float v = src[i] + bias;
            int row = co * 4 + (oh & 1) * 2 + (ow & 1);
            int c2 = (oh >> 1) * 7 + (ow >> 1);
            y1n[row * 49 + c2] = v;
            ls += v; lq += v * v;
        }
        atomicAdd(&ssum[co], ls);
        atomicAdd(&ssq[co], lq);
    }
    __syncthreads();
    if (tid < 64) {
        atomicAdd(&g_acc[64 + tid], (double)ssum[tid]);
        atomicAdd(&g_acc[128 + tid], (double)ssq[tid]);
    }
}

// ---------------- bn1+relu(y1) -> conv2 (WMMA tf32), store y2, stats2 ----------
// block = 1 image, 512 threads (16 warps), 2 blocks/SM.
// Warp (Nt 0..3, Mg 0..3): 2 Mtiles x 1 Ntile (8 Mtiles total).
__global__ void __launch_bounds__(512, 2) k_conv2(const float* __restrict__ w2,
                                                  const float* __restrict__ b2) {
    extern __shared__ float sm[];
    float* B    = sm;            // [128][72]
    float* Wc   = sm + 9216;     // [128][136]
    float* ssum = sm + 26624;    // 128
    float* ssq  = sm + 26752;    // 128
    int tid = threadIdx.x;
    int n = blockIdx.x;
    if (tid < 128) { ssum[tid] = 0.f; ssq[tid] = 0.f; }

    // zero B pad columns p=49..63
    for (int i = tid; i < 1920; i += 512) {
        B[(i / 15) * 72 + 49 + (i % 15)] = 0.f;
    }

    int wpi = tid >> 5;
    int Nt = wpi & 3, Mg = wpi >> 2;       // 4 Ntiles x 4 Mgroups
    wmma::fragment<wmma::accumulator, 16, 16, 8, float> cf[2];
#pragma unroll
    for (int m = 0; m < 2; m++) wmma::fill_fragment(cf[m], 0.f);
    wmma::fragment<wmma::matrix_a, 16, 16, 8, wmma::precision::tf32, wmma::row_major> af;
    wmma::fragment<wmma::matrix_b, 16, 16, 8, wmma::precision::tf32, wmma::row_major> bf;

    const float* y1n = g_y1 + (size_t)n * 256 * 49;
    for (int kc = 0; kc < 2; kc++) {
        __syncthreads();
        for (int i = tid; i < 16384; i += 512) {
            int co = i >> 7, kl = i & 127;
            Wc[co * 136 + kl] = tf32r(w2[co * 256 + kc * 128 + kl]);
        }
        // B-build: coalesced copy + bn1 + relu + tf32
        for (int idx = tid; idx < 6272; idx += 512) {   // 128 rows x 49 cols
            int rb = idx / 49;
            int j = idx - rb * 49;
            int gr = kc * 128 + rb;
            float sc = g_scale[32 + (gr >> 2)], sh = g_shift[32 + (gr >> 2)];
            float v = y1n[gr * 49 + j];
            B[rb * 72 + j] = tf32r(fmaxf(fmaf(v, sc, sh), 0.f));
        }
        __syncthreads();
#pragma unroll 4
        for (int ks = 0; ks < 16; ks++) {
            wmma::load_matrix_sync(bf, &B[ks * 8 * 72 + Nt * 16], 72);
#pragma unroll
            for (int m = 0; m < 2; m++) {
                int Mt = Mg * 2 + m;
                wmma::load_matrix_sync(af, &Wc[Mt * 16 * 136 + ks * 8], 136);
                wmma::mma_sync(cf[m], af, bf, cf[m]);
            }
        }
    }
    __syncthreads();
#pragma unroll
    for (int m = 0; m < 2; m++) {
        int Mt = Mg * 2 + m;
        wmma::store_matrix_sync(&B[Mt * 16 * 72 + Nt * 16], cf[m], 72,
                                wmma::mem_row_major);
    }
    __syncthreads();

    // bias + stats + y2 write — 4 threads per co row
    {
        int co = tid >> 2, q = tid & 3;
        int p0 = q * 13, cnt = (q < 3) ? 13 : 10;
        float bias = b2[co];
        float ls = 0.f, lq = 0.f;
        float* dst = g_y2 + (size_t)(n * 128 + co) * 49;
        const float* src = &B[co * 72 + p0];
#pragma unroll 13
        for (int i = 0; i < cnt; i++) {
            float v = src[i] + bias;
            dst[p0 + i] = v;
            ls += v; lq += v * v;
        }
        atomicAdd(&ssum[co], ls);
        atomicAdd(&ssq[co], lq);
    }
    __syncthreads();
    if (tid < 128) {
        atomicAdd(&g_acc[192 + tid], (double)ssum[tid]);
        atomicAdd(&g_acc[320 + tid], (double)ssq[tid]);
    }
}

// ---------------- bn2+relu + global avg pool + FC ----------------
__global__ void __launch_bounds__(128) k_head(const float* __restrict__ wfc,
                                              const float* __restrict__ bfc,
                                              float* __restrict__ out) {
    __shared__ float sraw[6272];
    __shared__ float pooled[128];
    int tid = threadIdx.x, n = blockIdx.x;
    const float* y2 = g_y2 + (size_t)n * 6272;
    for (int i = tid; i < 6272; i += 128) sraw[i] = y2[i];
    __syncthreads();
    {
        int c = tid;
        float sc = g_scale[96 + c], sh = g_shift[96 + c];
        float s = 0.f;
        const float* p = &sraw[c * 49];
#pragma unroll
        for (int i = 0; i < 49; i++) s += fmaxf(fmaf(p[i], sc, sh), 0.f);
        pooled[c] = s * (1.f / 49.f);
    }
    __syncthreads();
    if (tid < 10) {
        float o = bfc[tid];
        const float* wr = wfc + tid * 128;
#pragma unroll 8
        for (int c = 0; c < 128; c++) o = fmaf(pooled[c], wr[c], o);
        out[(size_t)n * 10 + tid] = o;
    }
}

// ---------------- launch ----------------
extern "C" void kernel_launch(void* const* d_in, const int* in_sizes, int n_in,
                              void* d_out, int out_size) {
    const float* x   = (const float*)d_in[0];
    const float* w0  = (const float*)d_in[1];
    const float* b0  = (const float*)d_in[2];
    const float* g0  = (const float*)d_in[3];
    const float* be0 = (const float*)d_in[4];
    const float* w1  = (const float*)d_in[5];
    const float* b1  = (const float*)d_in[6];
    const float* g1  = (const float*)d_in[7];
    const float* be1 = (const float*)d_in[8];
    const float* w2  = (const float*)d_in[9];
    const float* b2  = (const float*)d_in[10];
    const float* g2  = (const float*)d_in[11];
    const float* be2 = (const float*)d_in[12];
    const float* wfc = (const float*)d_in[13];
    const float* bfc = (const float*)d_in[14];
    float* out = (float*)d_out;

    cudaFuncSetAttribute(k_conv1, cudaFuncAttributeMaxDynamicSharedMemorySize, 104960);
    cudaFuncSetAttribute(k_conv2, cudaFuncAttributeMaxDynamicSharedMemorySize, 107520);

    k_zero<<<2, 256>>>();
    k_stats0<<<NB, 256>>>(x, w0, b0);
    k_fin<<<1, 128>>>(0, 32, 1.0 / (8192.0 * 784.0), g0, be0, 0);
    k_conv1<<<NB * 2, 512, 104960>>>(w1, b1);
    k_fin<<<1, 128>>>(64, 64, 1.0 / (8192.0 * 196.0), g1, be1, 32);
    k_conv2<<<NB, 512, 107520>>>(w2, b2);
    k_fin<<<1, 128>>>(192, 128, 1.0 / (8192.0 * 49.0), g2, be2, 96);
    k_head<<<NB, 128>>>(wfc, bfc, out);
}